// round 10
// baseline (speedup 1.0000x reference)
#include <cuda_runtime.h>
#include <cuda_bf16.h>

#define NFD 32
#define NOD 128
#define PST 129           // padded smem stride (odd -> conflict-free row access)
#define WPB 10            // warps per block
#define BT (WPB * 32)
#define PIV_THRESH 1e-4f  // min |pivot| below which we redo with partial pivoting

__global__ __launch_bounds__(BT, 1)
void slater_det_kernel(const int* __restrict__ n,
                       const float* __restrict__ Phi,
                       float* __restrict__ out,
                       int nsamples)
{
    __shared__ float Phi_sh[NFD * PST];
    __shared__ int   idx_sh[WPB][4][NFD + 1];   // +1: groups hit distinct banks

    const int tid  = threadIdx.x;
    const int lane = tid & 31;
    const int wid  = tid >> 5;
    const int q    = lane >> 3;   // sample group 0..3 within warp
    const int l    = lane & 7;    // lane within group

    // Stage Phi (32x128 fp32 = 16KB) into padded shared memory once per block.
    for (int t = tid; t < NFD * NOD; t += BT) {
        int i = t >> 7;
        int c = t & 127;
        Phi_sh[i * PST + c] = Phi[t];
    }
    __syncthreads();

    const unsigned FULL = 0xffffffffu;
    const int warps_total = gridDim.x * WPB;
    const int nquads = (nsamples + 3) >> 2;
    int gw = blockIdx.x * WPB + wid;

    for (int p = gw; p < nquads; p += warps_total) {
        int s0 = 4 * p;
        __syncwarp();   // prev iteration's idx_sh reads vs this one's writes

        // ---- Build idx for 4 samples (full warp per sample) ----
        #pragma unroll
        for (int t = 0; t < 4; t++) {
            int st = min(s0 + t, nsamples - 1);
            const int4 v = ((const int4*)(n + (size_t)st * NOD))[lane];
            unsigned m4 = (unsigned)(v.x != 0)
                        | ((unsigned)(v.y != 0) << 1)
                        | ((unsigned)(v.z != 0) << 2)
                        | ((unsigned)(v.w != 0) << 3);
            unsigned b0 = __ballot_sync(FULL, v.x != 0);
            unsigned b1 = __ballot_sync(FULL, v.y != 0);
            unsigned b2 = __ballot_sync(FULL, v.z != 0);
            unsigned b3 = __ballot_sync(FULL, v.w != 0);
            unsigned lowmask = (1u << lane) - 1u;
            int base = __popc(b0 & lowmask) + __popc(b1 & lowmask)
                     + __popc(b2 & lowmask) + __popc(b3 & lowmask);
            int i0 = base;
            if (m4 & 1u) idx_sh[wid][t][i0] = lane * 4 + 0;
            int i1 = i0 + (int)(m4 & 1u);
            if (m4 & 2u) idx_sh[wid][t][i1] = lane * 4 + 1;
            int i2 = i1 + (int)((m4 >> 1) & 1u);
            if (m4 & 4u) idx_sh[wid][t][i2] = lane * 4 + 2;
            int i3 = i2 + (int)((m4 >> 2) & 1u);
            if (m4 & 8u) idx_sh[wid][t][i3] = lane * 4 + 3;
        }
        __syncwarp();

        // ---- Gather: lane owns rows l, l+8, l+16, l+24 of its group's sample ----
        float r0a[NFD], r1a[NFD], r2a[NFD], r3a[NFD];
        #pragma unroll
        for (int j = 0; j < NFD; j++) {
            int c = idx_sh[wid][q][j];
            r0a[j] = Phi_sh[l * PST + c];
            r1a[j] = Phi_sh[(l + 8) * PST + c];
            r2a[j] = Phi_sh[(l + 16) * PST + c];
            r3a[j] = Phi_sh[(l + 24) * PST + c];
        }

        // ---- Fast path: pivot-free LU, 4 samples per warp ----
        float det  = 1.0f;
        float minp = 1e30f;

        #pragma unroll
        for (int k = 0; k < NFD; k++) {
            const int slot = k >> 3;              // which row-array holds row k
            const int src  = (k & 7) + (q << 3);  // its owner lane in this group
            float pl = (slot == 0) ? r0a[k] : (slot == 1) ? r1a[k]
                     : (slot == 2) ? r2a[k] : r3a[k];
            float piv = __shfl_sync(FULL, pl, src);
            minp = fminf(minp, fabsf(piv));
            det *= piv;
            float invp = __frcp_rn(piv);

            // Multipliers: row (l + 8m) is updated iff it lies below row k.
            float f0 = 0.0f, f1 = 0.0f, f2 = 0.0f, f3 = 0.0f;
            if (slot == 0) {
                f0 = (l > (k & 7)) ? r0a[k] * invp : 0.0f;
                f1 = r1a[k] * invp;
                f2 = r2a[k] * invp;
                f3 = r3a[k] * invp;
            } else if (slot == 1) {
                f1 = (l > (k & 7)) ? r1a[k] * invp : 0.0f;
                f2 = r2a[k] * invp;
                f3 = r3a[k] * invp;
            } else if (slot == 2) {
                f2 = (l > (k & 7)) ? r2a[k] * invp : 0.0f;
                f3 = r3a[k] * invp;
            } else {
                f3 = (l > (k & 7)) ? r3a[k] * invp : 0.0f;
            }

            #pragma unroll
            for (int j = k + 1; j < NFD; j++) {
                float pj = (slot == 0) ? r0a[j] : (slot == 1) ? r1a[j]
                         : (slot == 2) ? r2a[j] : r3a[j];
                float pv = __shfl_sync(FULL, pj, src);
                if (slot == 0) r0a[j] = fmaf(-f0, pv, r0a[j]);
                if (slot <= 1) r1a[j] = fmaf(-f1, pv, r1a[j]);
                if (slot <= 2) r2a[j] = fmaf(-f2, pv, r2a[j]);
                r3a[j] = fmaf(-f3, pv, r3a[j]);
            }
        }

        // per-group validity (piv broadcast within group -> group-uniform)
        int badme = ((minp < PIV_THRESH) || !isfinite(det)) ? 1 : 0;

        // ---- Rare fallback: redo bad samples with full-warp pivoted LU ----
        // Single code copy, runtime t loop (keeps I$ footprint bounded).
        #pragma unroll 1
        for (int t = 0; t < 4; t++) {
            int bad_t = __shfl_sync(FULL, badme, t << 3);
            if (bad_t) {
                float r[NFD];
                #pragma unroll
                for (int j = 0; j < NFD; j++)
                    r[j] = Phi_sh[lane * PST + idx_sh[wid][t][j]];

                unsigned active = FULL;
                float dfb = 1.0f;
                int inv_cnt = 0;
                #pragma unroll
                for (int k = 0; k < NFD; k++) {
                    float av = fabsf(r[k]);
                    unsigned key = (active & (1u << lane))
                                 ? ((__float_as_uint(av) & 0xffffffe0u) | (unsigned)lane)
                                 : 0u;
                    unsigned mx = __reduce_max_sync(FULL, key);
                    int pp = (int)(mx & 31u);
                    float piv = __shfl_sync(FULL, r[k], pp);
                    inv_cnt += __popc(active & ((1u << pp) - 1u));
                    active &= ~(1u << pp);
                    dfb *= piv;
                    float invp = (piv != 0.0f) ? __frcp_rn(piv) : 0.0f;
                    float f = (active & (1u << lane)) ? (r[k] * invp) : 0.0f;
                    #pragma unroll
                    for (int j = k + 1; j < NFD; j++) {
                        float pv = __shfl_sync(FULL, r[j], pp);
                        r[j] = fmaf(-f, pv, r[j]);
                    }
                }
                if (inv_cnt & 1) dfb = -dfb;
                if (q == t) det = dfb;
            }
        }

        if (l == 0 && (s0 + q) < nsamples)
            out[s0 + q] = det;
    }
}

extern "C" void kernel_launch(void* const* d_in, const int* in_sizes, int n_in,
                              void* d_out, int out_size)
{
    const int*   n_ptr = (const int*)d_in[0];      // n:   (B, 128) int32
    const float* Phi   = (const float*)d_in[1];    // Phi: (32, 128) float32
    float*       out   = (float*)d_out;            // det: (B,) float32

    int nsamples = in_sizes[0] / NOD;              // B = 131072

    // 1 reg-heavy block per SM (10 warps), grid-stride over sample quads.
    int grid = 148;
    slater_det_kernel<<<grid, BT>>>(n_ptr, Phi, out, nsamples);
}

// round 14
// speedup vs baseline: 5.1187x; 5.1187x over previous
#include <cuda_runtime.h>
#include <cuda_bf16.h>

#define NFD 32
#define NOD 128
#define PST 129           // padded smem stride (odd -> conflict-free column gather)
#define WPB 8             // warps per block
#define BT (WPB * 32)
#define PIV_THRESH 1e-4f  // min |pivot| below which we redo with partial pivoting

__global__ __launch_bounds__(BT, 2)
void slater_det_kernel(const int* __restrict__ n,
                       const float* __restrict__ Phi,
                       float* __restrict__ out,
                       int nsamples)
{
    __shared__ float Phi_sh[NFD * PST];
    __shared__ int   idx_sh[WPB][2][NFD];

    const int tid  = threadIdx.x;
    const int lane = tid & 31;
    const int wid  = tid >> 5;
    const int half = lane >> 4;       // 0: sample s0, 1: sample s0+1
    const int l    = lane & 15;       // lane within half

    // Stage Phi (32x128 fp32 = 16KB) into padded shared memory once per block.
    for (int t = tid; t < NFD * NOD; t += BT) {
        int i = t >> 7;
        int c = t & 127;
        Phi_sh[i * PST + c] = Phi[t];
    }
    __syncthreads();

    const unsigned FULL = 0xffffffffu;
    const int warps_total = (gridDim.x * BT) >> 5;
    const int npairs = nsamples >> 1;   // B even
    int p = (blockIdx.x * BT + tid) >> 5;

    // Software pipeline: preload this warp's first pair of n-vectors.
    int4 vA, vB;
    if (p < npairs) {
        vA = ((const int4*)(n + (size_t)(2 * p    ) * NOD))[lane];
        vB = ((const int4*)(n + (size_t)(2 * p + 1) * NOD))[lane];
    }

    for (; p < npairs; p += warps_total) {
        int s0 = 2 * p;
        __syncwarp();   // previous iteration's idx_sh reads vs this one's writes

        // ---- Build idx for BOTH samples from the prefetched vectors ----
        #pragma unroll
        for (int t = 0; t < 2; t++) {
            const int4 v = (t == 0) ? vA : vB;
            unsigned m4 = (unsigned)(v.x != 0)
                        | ((unsigned)(v.y != 0) << 1)
                        | ((unsigned)(v.z != 0) << 2)
                        | ((unsigned)(v.w != 0) << 3);
            unsigned b0 = __ballot_sync(FULL, v.x != 0);
            unsigned b1 = __ballot_sync(FULL, v.y != 0);
            unsigned b2 = __ballot_sync(FULL, v.z != 0);
            unsigned b3 = __ballot_sync(FULL, v.w != 0);
            unsigned lowmask = (1u << lane) - 1u;
            int base = __popc(b0 & lowmask) + __popc(b1 & lowmask)
                     + __popc(b2 & lowmask) + __popc(b3 & lowmask);
            int r0 = base;
            if (m4 & 1u) idx_sh[wid][t][r0] = lane * 4 + 0;
            int r1 = r0 + (int)(m4 & 1u);
            if (m4 & 2u) idx_sh[wid][t][r1] = lane * 4 + 1;
            int r2 = r1 + (int)((m4 >> 1) & 1u);
            if (m4 & 4u) idx_sh[wid][t][r2] = lane * 4 + 2;
            int r3 = r2 + (int)((m4 >> 2) & 1u);
            if (m4 & 8u) idx_sh[wid][t][r3] = lane * 4 + 3;
        }
        __syncwarp();

        // ---- Prefetch NEXT pair's n-vectors (latency hidden by LU below) ----
        {
            int pn = p + warps_total;
            if (pn >= npairs) pn = p;          // warp-uniform clamp, stays in-bounds
            vA = ((const int4*)(n + (size_t)(2 * pn    ) * NOD))[lane];
            vB = ((const int4*)(n + (size_t)(2 * pn + 1) * NOD))[lane];
        }

        // ---- Gather: lane owns rows l and l+16 of its half's sample ----
        float rlo[NFD], rhi[NFD];
        #pragma unroll
        for (int j = 0; j < NFD; j++) {
            int c = idx_sh[wid][half][j];
            rlo[j] = Phi_sh[l * PST + c];
            rhi[j] = Phi_sh[(l + 16) * PST + c];
        }

        // ---- Fast path: pivot-free LU, 2 samples per warp ----
        float det  = 1.0f;
        float minp = 1e30f;

        #pragma unroll
        for (int k = 0; k < NFD; k++) {
            const int src = (k & 15) + (half << 4);   // owner of row k in this half
            float pl = (k < 16) ? rlo[k] : rhi[k];
            float piv = __shfl_sync(FULL, pl, src);
            minp = fminf(minp, fabsf(piv));
            det *= piv;
            float invp = __frcp_rn(piv);

            if (k < 16) {
                float fLo = (l > k) ? (rlo[k] * invp) : 0.0f;
                float fHi = rhi[k] * invp;            // all hi rows are below k
                #pragma unroll
                for (int j = k + 1; j < NFD; j++) {
                    float pv = __shfl_sync(FULL, rlo[j], src);
                    rlo[j] = fmaf(-fLo, pv, rlo[j]);
                    rhi[j] = fmaf(-fHi, pv, rhi[j]);
                }
            } else {
                float fHi = (l + 16 > k) ? (rhi[k] * invp) : 0.0f;
                #pragma unroll
                for (int j = k + 1; j < NFD; j++) {
                    float pv = __shfl_sync(FULL, rhi[j], src);
                    rhi[j] = fmaf(-fHi, pv, rhi[j]);
                }
            }
        }

        // per-half validity (piv broadcast within half -> uniform per half)
        int badme = ((minp < PIV_THRESH) || !isfinite(det)) ? 1 : 0;
        int badA = __shfl_sync(FULL, badme, 0);
        int badB = __shfl_sync(FULL, badme, 16);

        // ---- Rare fallback: redo bad sample with full-warp pivoted LU ----
        #pragma unroll
        for (int t = 0; t < 2; t++) {
            if ((t == 0 ? badA : badB)) {
                float r[NFD];
                #pragma unroll
                for (int j = 0; j < NFD; j++)
                    r[j] = Phi_sh[lane * PST + idx_sh[wid][t][j]];

                unsigned active = FULL;
                float dfb = 1.0f;
                int inv_cnt = 0;
                #pragma unroll
                for (int k = 0; k < NFD; k++) {
                    float av = fabsf(r[k]);
                    unsigned key = (active & (1u << lane))
                                 ? ((__float_as_uint(av) & 0xffffffe0u) | (unsigned)lane)
                                 : 0u;
                    unsigned mx = __reduce_max_sync(FULL, key);
                    int pp = (int)(mx & 31u);
                    float piv = __shfl_sync(FULL, r[k], pp);
                    inv_cnt += __popc(active & ((1u << pp) - 1u));
                    active &= ~(1u << pp);
                    dfb *= piv;
                    float invp = (piv != 0.0f) ? __frcp_rn(piv) : 0.0f;
                    float f = (active & (1u << lane)) ? (r[k] * invp) : 0.0f;
                    #pragma unroll
                    for (int j = k + 1; j < NFD; j++) {
                        float pv = __shfl_sync(FULL, r[j], pp);
                        r[j] = fmaf(-f, pv, r[j]);
                    }
                }
                if (inv_cnt & 1) dfb = -dfb;
                if (half == t) det = dfb;
            }
        }

        if (l == 0)
            out[s0 + half] = det;
    }
}

extern "C" void kernel_launch(void* const* d_in, const int* in_sizes, int n_in,
                              void* d_out, int out_size)
{
    const int*   n_ptr = (const int*)d_in[0];      // n:   (B, 128) int32
    const float* Phi   = (const float*)d_in[1];    // Phi: (32, 128) float32
    float*       out   = (float*)d_out;            // det: (B,) float32

    int nsamples = in_sizes[0] / NOD;              // B = 131072 (even)

    // 148 SMs x 2 resident blocks (reg-heavy: 64-reg matrix per thread).
    int grid = 148 * 2;
    slater_det_kernel<<<grid, BT>>>(n_ptr, Phi, out, nsamples);
}